// round 4
// baseline (speedup 1.0000x reference)
#include <cuda_runtime.h>
#include <cuda_fp16.h>

// GraphMaxPooling: out[b,i,k] = sum_c max_j( adj[b,c,i,j] * x[b,j,k] )
// B=64, C=4, N=128, K=64. adj entries are exactly 0.0f or 1.0f.
//
// R3: smem-crossbar relief. Each warp now processes TWO i-rows, sharing the
// expensive distinct-address x LDS.128 pair per jb-iter between both rows
// (x smem wavefronts halve; adj loads are uniform-address broadcasts ~free).
// Block = 128 threads (4 warps, 8 rows), grid = 1024, launch_bounds(128,9):
// fully resident (1332 slots >= 1024), regs up to 56 for load batching/ILP.

#define GB 64
#define GC 4
#define GN 128
#define GK 64
#define XS_STRIDE 132   // half2 units: 132%32==4 -> conflict-free LDS.128 across lanes

__global__ __launch_bounds__(128, 9)
void GraphMaxPooling_82815559402085_kernel(const float* __restrict__ x,
                                           const float* __restrict__ adj,
                                           float* __restrict__ out) {
    // 16 blocks per b, 8 rows per block, 2 rows per warp.
    const int b       = blockIdx.x >> 4;
    const int rowBase = (blockIdx.x & 15) << 3;
    const int tid     = threadIdx.x;
    const int lane    = tid & 31;
    const int warp    = tid >> 5;           // 0..3
    const int r0      = warp << 1;          // local rows r0, r0+1
    const int r1      = r0 + 1;

    __shared__ __align__(16) __half2 xs[GK / 2][XS_STRIDE];  // [k2][j], ~16.9 KB
    __shared__ __align__(16) __half2 as_[8][GC][GN / 2];     // [row][c][jpair], 8 KB

    // ---- Stage x[b] (128 x 64 fp32) transposed into xs[k2][j] as half2 ----
    {
        const float4* xg = (const float4*)(x + (size_t)b * GN * GK);
        #pragma unroll
        for (int t = 0; t < 16; ++t) {
            int f4 = tid + 128 * t;            // 0..2047
            float4 v = xg[f4];
            int e  = f4 << 2;                  // element index
            int j  = e >> 6;                   // row (j)
            int k2 = (e & 63) >> 1;            // half2 column
            xs[k2][j]     = __floats2half2_rn(v.x, v.y);
            xs[k2 + 1][j] = __floats2half2_rn(v.z, v.w);
        }
    }

    // ---- Stage adj rows (8 i's x 4 c x 128 j) as half2 j-pairs ----
    #pragma unroll
    for (int c = 0; c < GC; ++c) {
        const float4* ag = (const float4*)(adj + (((size_t)b * GC + c) * GN + rowBase) * GN);
        #pragma unroll
        for (int t = 0; t < 2; ++t) {
            int f4 = tid + 128 * t;            // 0..255
            float4 v = ag[f4];
            int r  = f4 >> 5;                  // local row 0..7
            int j2 = (f4 & 31) << 1;           // half2-pair index
            as_[r][c][j2]     = __floats2half2_rn(v.x, v.y);
            as_[r][c][j2 + 1] = __floats2half2_rn(v.z, v.w);
        }
    }
    __syncthreads();

    const __half2* xrow = xs[lane];
    const __half2 NINF = __half2half2(__ushort_as_half((unsigned short)0xFC00));
    __half2 A0 = NINF, A1 = NINF, A2 = NINF, A3 = NINF;   // row r0, channels 0..3
    __half2 B0 = NINF, B1 = NINF, B2 = NINF, B3 = NINF;   // row r1, channels 0..3

    #pragma unroll 4
    for (int jb = 0; jb < GN; jb += 8) {
        // 8 x-values for my k-pair (shared by both rows): two LDS.128.
        uint4 xa = *(const uint4*)(xrow + jb);
        uint4 xb = *(const uint4*)(xrow + jb + 4);
        __half2 xv0 = *(__half2*)&xa.x, xv1 = *(__half2*)&xa.y;
        __half2 xv2 = *(__half2*)&xa.z, xv3 = *(__half2*)&xa.w;
        __half2 xv4 = *(__half2*)&xb.x, xv5 = *(__half2*)&xb.y;
        __half2 xv6 = *(__half2*)&xb.z, xv7 = *(__half2*)&xb.w;

        #pragma unroll
        for (int c = 0; c < GC; ++c) {
            // adjacency j-pairs for both rows: two broadcast LDS.128.
            uint4 avA = *(const uint4*)(&as_[r0][c][jb >> 1]);
            uint4 avB = *(const uint4*)(&as_[r1][c][jb >> 1]);

            __half2 a0 = *(__half2*)&avA.x, a1 = *(__half2*)&avA.y;
            __half2 a2 = *(__half2*)&avA.z, a3 = *(__half2*)&avA.w;
            __half2 pA0 = __hmul2(xv0, __low2half2(a0));
            __half2 pA1 = __hmul2(xv1, __high2half2(a0));
            __half2 pA2 = __hmul2(xv2, __low2half2(a1));
            __half2 pA3 = __hmul2(xv3, __high2half2(a1));
            __half2 pA4 = __hmul2(xv4, __low2half2(a2));
            __half2 pA5 = __hmul2(xv5, __high2half2(a2));
            __half2 pA6 = __hmul2(xv6, __low2half2(a3));
            __half2 pA7 = __hmul2(xv7, __high2half2(a3));
            __half2 mA = __hmax2(__hmax2(__hmax2(pA0, pA1), __hmax2(pA2, pA3)),
                                 __hmax2(__hmax2(pA4, pA5), __hmax2(pA6, pA7)));

            __half2 b0h = *(__half2*)&avB.x, b1h = *(__half2*)&avB.y;
            __half2 b2h = *(__half2*)&avB.z, b3h = *(__half2*)&avB.w;
            __half2 pB0 = __hmul2(xv0, __low2half2(b0h));
            __half2 pB1 = __hmul2(xv1, __high2half2(b0h));
            __half2 pB2 = __hmul2(xv2, __low2half2(b1h));
            __half2 pB3 = __hmul2(xv3, __high2half2(b1h));
            __half2 pB4 = __hmul2(xv4, __low2half2(b2h));
            __half2 pB5 = __hmul2(xv5, __high2half2(b2h));
            __half2 pB6 = __hmul2(xv6, __low2half2(b3h));
            __half2 pB7 = __hmul2(xv7, __high2half2(b3h));
            __half2 mB = __hmax2(__hmax2(__hmax2(pB0, pB1), __hmax2(pB2, pB3)),
                                 __hmax2(__hmax2(pB4, pB5), __hmax2(pB6, pB7)));

            if (c == 0)      { A0 = __hmax2(A0, mA); B0 = __hmax2(B0, mB); }
            else if (c == 1) { A1 = __hmax2(A1, mA); B1 = __hmax2(B1, mB); }
            else if (c == 2) { A2 = __hmax2(A2, mA); B2 = __hmax2(B2, mB); }
            else             { A3 = __hmax2(A3, mA); B3 = __hmax2(B3, mB); }
        }
    }

    // ---- fp32 channel sums + stores (lane owns k = 2*lane, 2*lane+1) ----
    {
        float2 f0 = __half22float2(A0), f1 = __half22float2(A1);
        float2 f2 = __half22float2(A2), f3 = __half22float2(A3);
        float sx = (f0.x + f1.x) + (f2.x + f3.x);
        float sy = (f0.y + f1.y) + (f2.y + f3.y);
        const int i = rowBase + r0;
        float2* o2 = (float2*)(out + ((size_t)b * GN + i) * GK);
        o2[lane] = make_float2(sx, sy);
    }
    {
        float2 f0 = __half22float2(B0), f1 = __half22float2(B1);
        float2 f2 = __half22float2(B2), f3 = __half22float2(B3);
        float sx = (f0.x + f1.x) + (f2.x + f3.x);
        float sy = (f0.y + f1.y) + (f2.y + f3.y);
        const int i = rowBase + r1;
        float2* o2 = (float2*)(out + ((size_t)b * GN + i) * GK);
        o2[lane] = make_float2(sx, sy);
    }
}

extern "C" void kernel_launch(void* const* d_in, const int* in_sizes, int n_in,
                              void* d_out, int out_size) {
    const float* x   = (const float*)d_in[0];   // (B, N, K) float32
    const float* adj = (const float*)d_in[1];   // (B, C, N, N) float32
    float* out       = (float*)d_out;           // (B, N, K) float32
    (void)in_sizes; (void)n_in; (void)out_size;

    GraphMaxPooling_82815559402085_kernel<<<GB * 16, 128>>>(x, adj, out);
}

// round 5
// speedup vs baseline: 1.2655x; 1.2655x over previous
#include <cuda_runtime.h>
#include <cuda_fp16.h>

// GraphMaxPooling: out[b,i,k] = sum_c max_j( adj[b,c,i,j] * x[b,j,k] )
// B=64, C=4, N=128, K=64. adj entries are exactly 0.0f or 1.0f.
//
// R4: algorithmic cut. Per b, precompute smem table
//   tbl[g][nib][k2] = max over set bits t of nib of half(x[b][4g+t][k-pair])
// (32 j-groups x 16 nibbles x 32 k-pairs = 64KB). Then per (row, c):
//   acc = max over 32 groups of tbl[g][nibble(mask,g)][...]  (one LDS.128
//   per lookup serving 8 k) -- eliminates all HMUL2 and 7/8 of the HMNMX2.
// Zero products: nib=0 -> -inf; final max(acc,0) when mask != all-ones.
// Warp = 4 rows x 8 k-chunks. 256 blocks x 256 threads, 67.6KB dyn smem.

#define GB 64
#define GC 4
#define GN 128
#define GK 64

#define TBL_WORDS (32 * 16 * 32)      // 16384 words = 64 KB
#define MSK_WORDS (32 * 4 * 4)        // 32 rows x 4 c x 4 words
#define SMEM_BYTES ((TBL_WORDS + MSK_WORDS) * 4)

__device__ __forceinline__ unsigned h2u(__half2 h) { return *(unsigned*)&h; }
__device__ __forceinline__ __half2 u2h(unsigned u) { return *(__half2*)&u; }

__global__ __launch_bounds__(256)
void GraphMaxPooling_82815559402085_kernel(const float* __restrict__ x,
                                           const float* __restrict__ adj,
                                           float* __restrict__ out) {
    extern __shared__ unsigned smem_dyn[];
    unsigned* tbl = smem_dyn;                 // [g][nib][k2]
    unsigned* msk = smem_dyn + TBL_WORDS;     // [row][c][word]

    const int b       = blockIdx.x >> 2;
    const int rowBase = (blockIdx.x & 3) << 5;   // 32 rows per block
    const int tid     = threadIdx.x;
    const int lane    = tid & 31;
    const int warp    = tid >> 5;                // 0..7

    const unsigned NINF = 0xFC00FC00u;           // half2(-inf,-inf)

    // ---- Build nibble-max table: warp per group, 4 rounds ----
    #pragma unroll
    for (int round = 0; round < 4; ++round) {
        const int g = warp + (round << 3);       // 0..31
        const float2* xr = (const float2*)(x + ((size_t)b * GN + (g << 2)) * GK);
        float2 f0 = xr[lane];                    // j = 4g+0, k = 2*lane..
        float2 f1 = xr[32 + lane];               // j = 4g+1
        float2 f2 = xr[64 + lane];               // j = 4g+2
        float2 f3 = xr[96 + lane];               // j = 4g+3
        __half2 h1 = __floats2half2_rn(f0.x, f0.y);   // bit 0
        __half2 h2 = __floats2half2_rn(f1.x, f1.y);   // bit 1
        __half2 h4 = __floats2half2_rn(f2.x, f2.y);   // bit 2
        __half2 h8 = __floats2half2_rn(f3.x, f3.y);   // bit 3
        __half2 m3  = __hmax2(h1, h2);
        __half2 m5  = __hmax2(h1, h4);
        __half2 m6  = __hmax2(h2, h4);
        __half2 m7  = __hmax2(m3, h4);
        __half2 m9  = __hmax2(h1, h8);
        __half2 m10 = __hmax2(h2, h8);
        __half2 m11 = __hmax2(m3, h8);
        __half2 m12 = __hmax2(h4, h8);
        __half2 m13 = __hmax2(m5, h8);
        __half2 m14 = __hmax2(m6, h8);
        __half2 m15 = __hmax2(m7, h8);
        unsigned* e = tbl + (g << 9) + lane;     // entry stride = 32 words
        e[0]   = NINF;
        e[32]  = h2u(h1);  e[64]  = h2u(h2);  e[96]  = h2u(m3);
        e[128] = h2u(h4);  e[160] = h2u(m5);  e[192] = h2u(m6);  e[224] = h2u(m7);
        e[256] = h2u(h8);  e[288] = h2u(m9);  e[320] = h2u(m10); e[352] = h2u(m11);
        e[384] = h2u(m12); e[416] = h2u(m13); e[448] = h2u(m14); e[480] = h2u(m15);
    }

    // ---- Build adjacency bitmasks: 32 rows x 4 c x 4 words via ballot ----
    {
        const float* adjB = adj + (size_t)b * GC * GN * GN;
        #pragma unroll 4
        for (int t = 0; t < 64; ++t) {
            int idx = (warp << 6) + t;           // 0..511: row*16 + c*4 + w
            int rr = idx >> 4;
            int cc = (idx >> 2) & 3;
            int ww = idx & 3;
            float a = adjB[((size_t)cc * GN + rowBase + rr) * GN + (ww << 5) + lane];
            unsigned bal = __ballot_sync(0xffffffffu, a != 0.0f);
            if (lane == 0) msk[idx] = bal;
        }
    }
    __syncthreads();

    // ---- Main: warp handles 4 rows; lane = (row-in-warp, k-chunk of 8) ----
    const int r   = lane >> 3;                   // 0..3
    const int row = (warp << 2) + r;             // block-local row 0..31
    const int kc  = lane & 7;                    // k-chunk: k in [8*kc, 8*kc+8)

    const unsigned* myMask = msk + (row << 4);
    const unsigned* tk     = tbl + (kc << 2);    // lane's 4-word slot in each entry

    float o0 = 0.f, o1 = 0.f, o2 = 0.f, o3 = 0.f;
    float o4 = 0.f, o5 = 0.f, o6 = 0.f, o7 = 0.f;

    #pragma unroll
    for (int c = 0; c < GC; ++c) {
        const uint4 mw = *(const uint4*)(myMask + (c << 2));
        __half2 a0 = u2h(NINF), a1 = u2h(NINF), a2 = u2h(NINF), a3 = u2h(NINF);
        const unsigned wv0 = mw.x, wv1 = mw.y, wv2 = mw.z, wv3 = mw.w;

        #pragma unroll
        for (int gw = 0; gw < 4; ++gw) {
            const unsigned w = (gw == 0) ? wv0 : (gw == 1) ? wv1 : (gw == 2) ? wv2 : wv3;
            #pragma unroll
            for (int gn = 0; gn < 8; ++gn) {
                const unsigned nib = (w >> (gn * 4)) & 15u;
                const uint4 v = *(const uint4*)(tk + (((gw << 3) + gn) << 9) + (nib << 5));
                a0 = __hmax2(a0, u2h(v.x));
                a1 = __hmax2(a1, u2h(v.y));
                a2 = __hmax2(a2, u2h(v.z));
                a3 = __hmax2(a3, u2h(v.w));
            }
        }

        // Zero-product fixup: any unset j contributes an exact 0 to the max.
        if ((wv0 & wv1 & wv2 & wv3) != 0xffffffffu) {
            const __half2 Z = __float2half2_rn(0.f);
            a0 = __hmax2(a0, Z); a1 = __hmax2(a1, Z);
            a2 = __hmax2(a2, Z); a3 = __hmax2(a3, Z);
        }

        float2 f;
        f = __half22float2(a0); o0 += f.x; o1 += f.y;
        f = __half22float2(a1); o2 += f.x; o3 += f.y;
        f = __half22float2(a2); o4 += f.x; o5 += f.y;
        f = __half22float2(a3); o6 += f.x; o7 += f.y;
    }

    // ---- Store 8 fp32 (two float4) ----
    float* op = out + ((size_t)b * GN + rowBase + row) * GK + (kc << 3);
    *(float4*)op       = make_float4(o0, o1, o2, o3);
    *(float4*)(op + 4) = make_float4(o4, o5, o6, o7);
}

extern "C" void kernel_launch(void* const* d_in, const int* in_sizes, int n_in,
                              void* d_out, int out_size) {
    const float* x   = (const float*)d_in[0];   // (B, N, K) float32
    const float* adj = (const float*)d_in[1];   // (B, C, N, N) float32
    float* out       = (float*)d_out;           // (B, N, K) float32
    (void)in_sizes; (void)n_in; (void)out_size;

    cudaFuncSetAttribute(GraphMaxPooling_82815559402085_kernel,
                         cudaFuncAttributeMaxDynamicSharedMemorySize, SMEM_BYTES);
    GraphMaxPooling_82815559402085_kernel<<<GB * 4, 256, SMEM_BYTES>>>(x, adj, out);
}